// round 1
// baseline (speedup 1.0000x reference)
#include <cuda_runtime.h>
#include <math.h>
#include <stdint.h>

// Problem constants
#define TLEN 4096
#define BSZ 8

// ---------------- device scratch (no allocation allowed) ----------------
__device__ float g_x1[BSZ * 64 * TLEN];
__device__ float g_x2[BSZ * 128 * TLEN];
__device__ float g_x3[BSZ * 256 * TLEN];
__device__ float g_x4[BSZ * 512 * TLEN];
__device__ float g_x5[BSZ * 512 * TLEN];
__device__ float g_zqT[BSZ * 512 * TLEN];          // z_q in [b][d][t] layout
__device__ float g_w2T[64 * 5 * 128];
__device__ float g_w3T[128 * 5 * 256];
__device__ float g_w4T[256 * 3 * 512];
__device__ float g_w5T[512 * 3 * 512];
__device__ float g_hwT[512 * 256];                 // head weights [d][h*64+v]
__device__ float g_part[2048];                     // vq-loss partials (32*8*8)

// Output packing offsets (float32 concat of (a_tokens, b_logits, vq_loss))
#define OFF_A 0
#define OFF_B (BSZ * 8 * TLEN)                     // 262144
#define OFF_L (OFF_B + BSZ * 4 * TLEN * 64)        // 8650752

// ---------------- conv1: Cin=1, k=7, ELU ----------------
__global__ void conv1_kernel(const float* __restrict__ audio,
                             const float* __restrict__ w1,
                             const float* __restrict__ b1,
                             float* __restrict__ y) {
    __shared__ float sx[128 + 6];
    __shared__ float sw[64 * 7];
    __shared__ float sb[64];
    const int b = blockIdx.y;
    const int t0 = blockIdx.x * 128;
    const int tid = threadIdx.x;

    for (int i = tid; i < 134; i += 128) {
        int t = t0 - 6 + i;
        sx[i] = (t >= 0) ? audio[(size_t)b * TLEN + t] : 0.f;
    }
    for (int i = tid; i < 448; i += 128) sw[i] = w1[i];
    if (tid < 64) sb[tid] = b1[tid];
    __syncthreads();

    float xv[7];
#pragma unroll
    for (int j = 0; j < 7; j++) xv[j] = sx[tid + j];

    for (int c = 0; c < 64; c++) {
        float acc = sb[c];
#pragma unroll
        for (int j = 0; j < 7; j++) acc += sw[c * 7 + j] * xv[j];
        acc = acc > 0.f ? acc : expm1f(acc);
        y[((size_t)b * 64 + c) * TLEN + t0 + tid] = acc;
    }
}

// ---------------- weight transposes ----------------
__global__ void transpose_w(const float* __restrict__ w, float* __restrict__ wT,
                            int CIN, int COUT, int K) {
    int i = blockIdx.x * 256 + threadIdx.x;
    int total = CIN * K * COUT;
    if (i < total) {
        int co = i % COUT;
        int j = (i / COUT) % K;
        int ci = i / (COUT * K);
        wT[i] = w[((size_t)co * CIN + ci) * K + j];
    }
}

__global__ void transpose_head(const float* __restrict__ hw, float* __restrict__ hwT) {
    int i = blockIdx.x * 256 + threadIdx.x;   // total 512*256
    if (i < 512 * 256) {
        int co = i % 256;       // h*64+v
        int d = i / 256;
        int h = co >> 6, v = co & 63;
        hwT[i] = hw[((size_t)h * 512 + d) * 64 + v];
    }
}

// ---------------- generic conv-as-GEMM ----------------
// x: [B][CIN][T], wT: [CIN*K][COUT], y: conv -> [B][COUT][T]; HEAD -> bhtv logits
template <int CIN, int COUT, int K, int CI_CHUNK, int ELU, int HEAD>
__global__ __launch_bounds__(256)
void conv_gemm(const float* __restrict__ x, const float* __restrict__ wT,
               const float* __restrict__ bias, float* __restrict__ y) {
    constexpr int TT = 64;
    constexpr int CO_TILE = 64;
    constexpr int TXN = TT / 4;        // 16
    constexpr int XROW = TT + 8;       // 72 (float4-window safe, padded)

    __shared__ float xs[CI_CHUNK][XROW];
    __shared__ float ws[CI_CHUNK][K][CO_TILE];

    const int b = blockIdx.z;
    const int t0 = blockIdx.x * TT;
    const int co0 = blockIdx.y * CO_TILE;
    const int tid = threadIdx.x;
    const int tx = tid % TXN, ty = tid / TXN;
    const int tb = tx * 4;

    float acc[4][4];
#pragma unroll
    for (int r = 0; r < 4; r++) {
        float bb = bias[co0 + ty * 4 + r];
#pragma unroll
        for (int j = 0; j < 4; j++) acc[r][j] = bb;
    }

    for (int ci0 = 0; ci0 < CIN; ci0 += CI_CHUNK) {
        __syncthreads();
        // load x tile (coalesced over t)
        for (int i = tid; i < CI_CHUNK * XROW; i += 256) {
            int cc = i / XROW, p = i % XROW;
            int t = t0 - (K - 1) + p;
            float v = 0.f;
            if (t >= 0 && t < TLEN)
                v = x[((size_t)b * CIN + ci0 + cc) * TLEN + t];
            xs[cc][p] = v;
        }
        // load w tile (coalesced over co)
        for (int i = tid; i < CI_CHUNK * K * CO_TILE; i += 256) {
            int cc = i / (K * CO_TILE);
            int rem = i % (K * CO_TILE);
            int j = rem / CO_TILE;
            int co = rem % CO_TILE;
            ws[cc][j][co] = wT[((size_t)(ci0 + cc) * K + j) * COUT + co0 + co];
        }
        __syncthreads();

#pragma unroll 2
        for (int cc = 0; cc < CI_CHUNK; cc++) {
            float4 xa = *(const float4*)&xs[cc][tb];
            float4 xb = *(const float4*)&xs[cc][tb + 4];
            float xv[8] = {xa.x, xa.y, xa.z, xa.w, xb.x, xb.y, xb.z, xb.w};
#pragma unroll
            for (int j = 0; j < K; j++) {
                float4 wv = *(const float4*)&ws[cc][j][ty * 4];
                float wr[4] = {wv.x, wv.y, wv.z, wv.w};
#pragma unroll
                for (int r = 0; r < 4; r++)
#pragma unroll
                    for (int lt = 0; lt < 4; lt++)
                        acc[r][lt] += wr[r] * xv[lt + j];
            }
        }
    }

    if (HEAD) {
        const int h = blockIdx.y;   // COUT=256, CO_TILE=64 => y-dim is head
#pragma unroll
        for (int lt = 0; lt < 4; lt++) {
            int t = t0 + tb + lt;
            float4 o = make_float4(acc[0][lt], acc[1][lt], acc[2][lt], acc[3][lt]);
            *(float4*)&y[(((size_t)b * 4 + h) * TLEN + t) * 64 + ty * 4] = o;
        }
    } else {
#pragma unroll
        for (int r = 0; r < 4; r++) {
            float4 o;
            float* op = &o.x;
#pragma unroll
            for (int lt = 0; lt < 4; lt++) {
                float a = acc[r][lt];
                if (ELU) a = a > 0.f ? a : expm1f(a);
                op[lt] = a;
            }
            *(float4*)&y[((size_t)b * COUT + co0 + ty * 4 + r) * TLEN + t0 + tb] = o;
        }
    }
}

// ---------------- VQ: fused dist-GEMM + argmin + gather + loss ----------------
// block: 256 thr, tile 128 tokens x 64 codes (16 code-chunks of 1024)
// smem floats: ztT 64*128, ctT 64*68, znorm 128, cnorm 64,
//              redv 1024, redi 1024(int), besti 128(int), qs 64*132
#define VQ_ZT 0
#define VQ_CT (64 * 128)
#define VQ_ZN (VQ_CT + 64 * 68)
#define VQ_CN (VQ_ZN + 128)
#define VQ_RV (VQ_CN + 64)
#define VQ_RI (VQ_RV + 1024)
#define VQ_BI (VQ_RI + 1024)
#define VQ_QS (VQ_BI + 128)
#define VQ_SMEM_FLOATS (VQ_QS + 64 * 132)
#define VQ_SMEM_BYTES (VQ_SMEM_FLOATS * 4)

__global__ __launch_bounds__(256)
void vq_kernel(const float* __restrict__ x5, const float* __restrict__ cbk,
               float* __restrict__ zqT, float* __restrict__ out_a,
               float* __restrict__ partial) {
    extern __shared__ float sm[];
    float* ztT = sm + VQ_ZT;          // [64][128]
    float* ctT = sm + VQ_CT;          // [64][68]
    float* znorm = sm + VQ_ZN;        // [128]
    float* cnorm = sm + VQ_CN;        // [64]
    float* redv = sm + VQ_RV;         // [128*8]
    int*   redi = (int*)(sm + VQ_RI); // [128*8]
    int*   besti = (int*)(sm + VQ_BI);// [128]
    float* qs = sm + VQ_QS;           // [64][132]

    const int b = blockIdx.z, g = blockIdx.y;
    const int t0 = blockIdx.x * 128;
    const int tid = threadIdx.x;
    const int lane = tid & 31, warp = tid >> 5;
    const int warpM = warp & 3, warpN = warp >> 2;  // 4 x 2
    const int lm = lane & 7, ln = lane >> 3;        // 8 x 4
    const int trow = warpM * 32 + lm * 4;           // 4 tokens per thread
    const int cbase = warpN * 32 + ln * 8;          // 8 codes per thread

    // load z tile (coalesced over t), layout [d][t]
    for (int i = tid; i < 64 * 128; i += 256) {
        int d = i >> 7, lt = i & 127;
        ztT[d * 128 + lt] = x5[(((size_t)b * 512) + (g << 6) + d) * TLEN + t0 + lt];
    }
    __syncthreads();
    if (tid < 128) {
        float s = 0.f;
#pragma unroll 8
        for (int d = 0; d < 64; d++) { float v = ztT[d * 128 + tid]; s += v * v; }
        znorm[tid] = s;
    }
    __syncthreads();

    float zn[4];
#pragma unroll
    for (int a = 0; a < 4; a++) zn[a] = znorm[trow + a];

    float bv[4];
    int bi[4];
#pragma unroll
    for (int a = 0; a < 4; a++) { bv[a] = 3.4e38f; bi[a] = 0; }

    for (int k0 = 0; k0 < 1024; k0 += 64) {
        __syncthreads();   // previous chunk's compute done before ctT reuse
        // load code chunk transposed: ctT[d][kk]
        for (int i = tid; i < 64 * 64; i += 256) {
            int kk = i >> 6, d = i & 63;
            ctT[d * 68 + kk] = cbk[((size_t)g * 1024 + k0 + kk) * 64 + d];
        }
        __syncthreads();
        if (tid < 64) {
            float s = 0.f;
#pragma unroll 8
            for (int d = 0; d < 64; d++) { float v = ctT[d * 68 + tid]; s += v * v; }
            cnorm[tid] = s;
        }
        __syncthreads();

        float acc[4][8];
#pragma unroll
        for (int a = 0; a < 4; a++)
#pragma unroll
            for (int c = 0; c < 8; c++) acc[a][c] = 0.f;

#pragma unroll 4
        for (int d = 0; d < 64; d++) {
            float4 za = *(const float4*)&ztT[d * 128 + trow];
            float4 c0 = *(const float4*)&ctT[d * 68 + cbase];
            float4 c1 = *(const float4*)&ctT[d * 68 + cbase + 4];
            float zz[4] = {za.x, za.y, za.z, za.w};
            float cc[8] = {c0.x, c0.y, c0.z, c0.w, c1.x, c1.y, c1.z, c1.w};
#pragma unroll
            for (int a = 0; a < 4; a++)
#pragma unroll
                for (int c = 0; c < 8; c++) acc[a][c] += zz[a] * cc[c];
        }
#pragma unroll
        for (int a = 0; a < 4; a++) {
#pragma unroll
            for (int c = 0; c < 8; c++) {
                float dist = zn[a] + cnorm[cbase + c] - 2.f * acc[a][c];
                int idx = k0 + cbase + c;
                if (dist < bv[a]) { bv[a] = dist; bi[a] = idx; }  // strict < keeps first
            }
        }
    }

    // cross-thread argmin reduction (8 contributors per token)
    __syncthreads();
#pragma unroll
    for (int a = 0; a < 4; a++) {
        int tok = trow + a;
        int slot = warpN * 4 + ln;
        redv[tok * 8 + slot] = bv[a];
        redi[tok * 8 + slot] = bi[a];
    }
    __syncthreads();
    if (tid < 128) {
        float best = redv[tid * 8];
        int bidx = redi[tid * 8];
#pragma unroll
        for (int s = 1; s < 8; s++) {
            float v = redv[tid * 8 + s];
            int ii = redi[tid * 8 + s];
            if (v < best || (v == best && ii < bidx)) { best = v; bidx = ii; }
        }
        besti[tid] = bidx;
        out_a[((size_t)b * 8 + g) * TLEN + t0 + tid] = (float)bidx;
    }
    __syncthreads();

    // gather q (coalesced codebook reads), exact loss, stage q for coalesced store
    float ls = 0.f;
    for (int i = tid; i < 64 * 128; i += 256) {
        int d = i & 63, lt = i >> 6;
        float qv = cbk[((size_t)g * 1024 + besti[lt]) * 64 + d];
        float df = qv - ztT[d * 128 + lt];
        ls += df * df;
        qs[d * 132 + lt] = qv;
    }
    __syncthreads();
    for (int i = tid; i < 64 * 128; i += 256) {
        int lt = i & 127, d = i >> 7;
        zqT[(((size_t)b * 512) + (g << 6) + d) * TLEN + t0 + lt] = qs[d * 132 + lt];
    }

    // deterministic block loss reduction (redv reused)
    redv[tid] = ls;
    __syncthreads();
    for (int s = 128; s > 0; s >>= 1) {
        if (tid < s) redv[tid] += redv[tid + s];
        __syncthreads();
    }
    if (tid == 0)
        partial[((size_t)b * 8 + g) * 32 + blockIdx.x] = redv[0];
}

// ---------------- final deterministic loss sum ----------------
__global__ void loss_kernel(const float* __restrict__ partial, float* __restrict__ out) {
    __shared__ float s[256];
    int tid = threadIdx.x;
    float v = 0.f;
    for (int i = tid; i < 2048; i += 256) v += partial[i];
    s[tid] = v;
    __syncthreads();
    for (int k = 128; k > 0; k >>= 1) {
        if (tid < k) s[tid] += s[tid + k];
        __syncthreads();
    }
    if (tid == 0) out[OFF_L] = s[0] * (1.f / (8.f * 4096.f * 64.f));
}

// ---------------- launch ----------------
extern "C" void kernel_launch(void* const* d_in, const int* in_sizes, int n_in,
                              void* d_out, int out_size) {
    const float* audio = (const float*)d_in[0];
    const float* w1 = (const float*)d_in[1];
    const float* b1 = (const float*)d_in[2];
    const float* w2 = (const float*)d_in[3];
    const float* b2 = (const float*)d_in[4];
    const float* w3 = (const float*)d_in[5];
    const float* b3 = (const float*)d_in[6];
    const float* w4 = (const float*)d_in[7];
    const float* b4 = (const float*)d_in[8];
    const float* w5 = (const float*)d_in[9];
    const float* b5 = (const float*)d_in[10];
    const float* codebooks = (const float*)d_in[11];
    const float* head_w = (const float*)d_in[12];
    const float* head_b = (const float*)d_in[13];
    float* out = (float*)d_out;

    float *x1, *x2, *x3, *x4, *x5, *zqT, *w2T, *w3T, *w4T, *w5T, *hwT, *part;
    cudaGetSymbolAddress((void**)&x1, g_x1);
    cudaGetSymbolAddress((void**)&x2, g_x2);
    cudaGetSymbolAddress((void**)&x3, g_x3);
    cudaGetSymbolAddress((void**)&x4, g_x4);
    cudaGetSymbolAddress((void**)&x5, g_x5);
    cudaGetSymbolAddress((void**)&zqT, g_zqT);
    cudaGetSymbolAddress((void**)&w2T, g_w2T);
    cudaGetSymbolAddress((void**)&w3T, g_w3T);
    cudaGetSymbolAddress((void**)&w4T, g_w4T);
    cudaGetSymbolAddress((void**)&w5T, g_w5T);
    cudaGetSymbolAddress((void**)&hwT, g_hwT);
    cudaGetSymbolAddress((void**)&part, g_part);

    cudaFuncSetAttribute(vq_kernel, cudaFuncAttributeMaxDynamicSharedMemorySize,
                         VQ_SMEM_BYTES);

    // weight prep
    transpose_w<<<(64 * 5 * 128 + 255) / 256, 256>>>(w2, w2T, 64, 128, 5);
    transpose_w<<<(128 * 5 * 256 + 255) / 256, 256>>>(w3, w3T, 128, 256, 5);
    transpose_w<<<(256 * 3 * 512 + 255) / 256, 256>>>(w4, w4T, 256, 512, 3);
    transpose_w<<<(512 * 3 * 512 + 255) / 256, 256>>>(w5, w5T, 512, 512, 3);
    transpose_head<<<(512 * 256 + 255) / 256, 256>>>(head_w, hwT);

    // encoder
    conv1_kernel<<<dim3(32, 8), 128>>>(audio, w1, b1, x1);
    conv_gemm<64, 128, 5, 16, 1, 0><<<dim3(64, 2, 8), 256>>>(x1, w2T, b2, x2);
    conv_gemm<128, 256, 5, 16, 1, 0><<<dim3(64, 4, 8), 256>>>(x2, w3T, b3, x3);
    conv_gemm<256, 512, 3, 32, 1, 0><<<dim3(64, 8, 8), 256>>>(x3, w4T, b4, x4);
    conv_gemm<512, 512, 3, 32, 0, 0><<<dim3(64, 8, 8), 256>>>(x4, w5T, b5, x5);

    // VQ + heads + loss
    vq_kernel<<<dim3(32, 8, 8), 256, VQ_SMEM_BYTES>>>(x5, codebooks, zqT, out + OFF_A, part);
    conv_gemm<512, 256, 1, 32, 0, 1><<<dim3(64, 4, 8), 256>>>(zqT, hwT, head_b, out + OFF_B);
    loss_kernel<<<1, 256>>>(part, out);
}